// round 1
// baseline (speedup 1.0000x reference)
#include <cuda_runtime.h>
#include <cuda_bf16.h>

// ---------------- problem constants ----------------
#define BATCH 4
#define SEQ   4096
#define DIM   1024
#define HEADS 16
#define DHEAD 64
#define INNER 1024          // HEADS*DHEAD
#define MROWS (BATCH*SEQ)   // 16384
#define QKVN  (3*INNER)     // 3072
#define LN_EPS 1e-5f

// ---------------- scratch (device globals; no allocs allowed) ----------------
__device__ float g_q[BATCH*HEADS*SEQ*DHEAD];   // [B,H,N,D] relu'd
__device__ float g_k[BATCH*HEADS*SEQ*DHEAD];   // [B,H,N,D] relu'd
__device__ float g_v[BATCH*HEADS*SEQ*DHEAD];   // [B,H,N,D]
__device__ float g_kvp[64*8*64*64];            // [BH, split, 64, 64]
__device__ float g_kv[64*64*64];               // [BH, 64, 64]
__device__ float g_o[MROWS*INNER];             // [B,N,INNER] o -> LN in place

// =====================================================================
// Kernel 1: qkv = x @ w_qkv ; relu on q,k ; scatter to [B,H,N,D]
// Tiled SGEMM: BM=BN=128, BK=8, 256 threads, 8x8 per thread (4+4 split)
// =====================================================================
__global__ __launch_bounds__(256)
void qkv_gemm(const float* __restrict__ A, const float* __restrict__ Bm)
{
    __shared__ float As[8][128];
    __shared__ float Bs[8][128];

    const int bm = blockIdx.y;          // 0..127 (M tiles)
    const int bn = blockIdx.x;          // 0..23  (N tiles)
    const int tid = threadIdx.x;

    // A load: one float4 per thread (128 rows x 8 cols)
    const int arow = tid >> 1;
    const int acol = (tid & 1) << 2;
    // B load: one float4 per thread (8 rows x 128 cols)
    const int brow = tid >> 5;
    const int bcol = (tid & 31) << 2;

    const int ty = tid >> 4;            // 0..15
    const int tx = tid & 15;            // 0..15

    float acc[8][8];
    #pragma unroll
    for (int i = 0; i < 8; i++)
        #pragma unroll
        for (int j = 0; j < 8; j++) acc[i][j] = 0.f;

    const float* Aptr = A + (long)(bm*128 + arow)*DIM + acol;
    const float* Bptr = Bm + (long)brow*QKVN + bn*128 + bcol;

    for (int k0 = 0; k0 < DIM; k0 += 8) {
        float4 av = *(const float4*)(Aptr + k0);
        As[acol+0][arow] = av.x;
        As[acol+1][arow] = av.y;
        As[acol+2][arow] = av.z;
        As[acol+3][arow] = av.w;
        *(float4*)&Bs[brow][bcol] = *(const float4*)(Bptr + (long)k0*QKVN);
        __syncthreads();

        #pragma unroll
        for (int kk = 0; kk < 8; kk++) {
            float4 a0 = *(const float4*)&As[kk][ty*4];
            float4 a1 = *(const float4*)&As[kk][ty*4 + 64];
            float4 b0 = *(const float4*)&Bs[kk][tx*4];
            float4 b1 = *(const float4*)&Bs[kk][tx*4 + 64];
            float a[8] = {a0.x,a0.y,a0.z,a0.w,a1.x,a1.y,a1.z,a1.w};
            float b[8] = {b0.x,b0.y,b0.z,b0.w,b1.x,b1.y,b1.z,b1.w};
            #pragma unroll
            for (int i = 0; i < 8; i++)
                #pragma unroll
                for (int j = 0; j < 8; j++)
                    acc[i][j] = fmaf(a[i], b[j], acc[i][j]);
        }
        __syncthreads();
    }

    // epilogue: scatter with relu into q/k/v head layout
    #pragma unroll
    for (int i = 0; i < 8; i++) {
        int gm = bm*128 + (i < 4 ? ty*4 + i : 64 + ty*4 + (i-4));
        int b = gm >> 12;               // /4096
        int n = gm & 4095;
        #pragma unroll
        for (int j = 0; j < 8; j++) {
            int gn = bn*128 + (j < 4 ? tx*4 + j : 64 + tx*4 + (j-4));
            int part = gn >> 10;        // 0=q 1=k 2=v
            int jj = gn & 1023;
            int h = jj >> 6, d = jj & 63;
            long dst = ((long)((b*HEADS + h)*SEQ + n))*DHEAD + d;
            float val = acc[i][j];
            if (part == 0)      g_q[dst] = fmaxf(val, 0.f);
            else if (part == 1) g_k[dst] = fmaxf(val, 0.f);
            else                g_v[dst] = val;
        }
    }
}

// =====================================================================
// Kernel 2: kv partials: per (bh, split) block reduces 512 n-rows
// =====================================================================
__global__ __launch_bounds__(256)
void kv_partial()
{
    const int bh = blockIdx.x >> 3;
    const int split = blockIdx.x & 7;
    __shared__ float Ks[32][64];
    __shared__ float Vs[32][64];

    const int tid = threadIdx.x;
    const int tm = (tid >> 4) << 2;     // 0..60
    const int tn = (tid & 15) << 2;     // 0..60
    float acc[4][4] = {{0.f}};

    const float* kbase = g_k + ((long)bh*SEQ + split*512)*DHEAD;
    const float* vbase = g_v + ((long)bh*SEQ + split*512)*DHEAD;

    for (int n0 = 0; n0 < 512; n0 += 32) {
        #pragma unroll
        for (int r = 0; r < 2; r++) {
            int idx = tid + r*256;      // 0..511 float4 slots
            int row = idx >> 4;
            int col = (idx & 15) << 2;
            *(float4*)&Ks[row][col] = *(const float4*)(kbase + (long)(n0+row)*DHEAD + col);
            *(float4*)&Vs[row][col] = *(const float4*)(vbase + (long)(n0+row)*DHEAD + col);
        }
        __syncthreads();
        #pragma unroll
        for (int nn = 0; nn < 32; nn++) {
            float4 a = *(const float4*)&Ks[nn][tm];
            float4 b = *(const float4*)&Vs[nn][tn];
            float av[4] = {a.x,a.y,a.z,a.w};
            float bv[4] = {b.x,b.y,b.z,b.w};
            #pragma unroll
            for (int i = 0; i < 4; i++)
                #pragma unroll
                for (int j = 0; j < 4; j++)
                    acc[i][j] = fmaf(av[i], bv[j], acc[i][j]);
        }
        __syncthreads();
    }

    float* dst = g_kvp + (long)blockIdx.x*4096;
    #pragma unroll
    for (int i = 0; i < 4; i++)
        #pragma unroll
        for (int j = 0; j < 4; j++)
            dst[(tm+i)*64 + tn + j] = acc[i][j];
}

// =====================================================================
// Kernel 3: reduce 8 splits -> g_kv   (deterministic, no atomics)
// =====================================================================
__global__ void kv_reduce()
{
    int idx = blockIdx.x*256 + threadIdx.x;   // 262144 total
    int bh = idx >> 12;
    int rem = idx & 4095;
    float s = 0.f;
    #pragma unroll
    for (int sp = 0; sp < 8; sp++)
        s += g_kvp[((long)(bh*8 + sp))*4096 + rem];
    g_kv[idx] = s;
}

// =====================================================================
// Kernel 4: o = q @ kv per (b,h); write to [B,N,INNER]
// block: 128 q-rows, kv (64x64) resident in smem
// =====================================================================
__global__ __launch_bounds__(256)
void o_gemm()
{
    const int bh = blockIdx.x >> 5;     // 0..63
    const int mt = blockIdx.x & 31;     // 0..31 (128-row tiles)
    const int b = bh >> 4, h = bh & 15;

    __shared__ float KVs[64][64];       // 16 KB
    __shared__ float Qs[128][64];       // 32 KB  (total 48 KB)

    const int tid = threadIdx.x;

    #pragma unroll
    for (int r = 0; r < 4; r++) {
        int idx = tid + r*256;          // 1024 float4 slots
        int row = idx >> 4;
        int col = (idx & 15) << 2;
        *(float4*)&KVs[row][col] = *(const float4*)(g_kv + (long)bh*4096 + row*64 + col);
    }
    const float* qbase = g_q + ((long)bh*SEQ + mt*128)*DHEAD;
    #pragma unroll
    for (int r = 0; r < 8; r++) {
        int idx = tid + r*256;          // 2048 float4 slots
        int row = idx >> 4;             // stride: 16 float4 per row
        int col = (idx & 15) << 2;
        *(float4*)&Qs[row][col] = *(const float4*)(qbase + (long)row*DHEAD + col);
    }
    __syncthreads();

    const int ty = tid >> 4;            // 0..15 -> 8 rows each
    const int tx = tid & 15;            // 0..15 -> 4 cols each
    float acc[8][4] = {{0.f}};

    #pragma unroll 8
    for (int kk = 0; kk < 64; kk++) {
        float4 bv = *(const float4*)&KVs[kk][tx*4];
        float bb[4] = {bv.x,bv.y,bv.z,bv.w};
        #pragma unroll
        for (int i = 0; i < 8; i++) {
            float a = Qs[ty*8 + i][kk];
            #pragma unroll
            for (int j = 0; j < 4; j++)
                acc[i][j] = fmaf(a, bb[j], acc[i][j]);
        }
    }

    #pragma unroll
    for (int i = 0; i < 8; i++) {
        long row = (long)(b*SEQ + mt*128 + ty*8 + i);
        float* dst = g_o + row*INNER + h*DHEAD + tx*4;
        float4 v = {acc[i][0], acc[i][1], acc[i][2], acc[i][3]};
        *(float4*)dst = v;
    }
}

// =====================================================================
// Kernel 5: LayerNorm in place over INNER, apply gamma/beta
// =====================================================================
__global__ __launch_bounds__(256)
void layernorm_rows(const float* __restrict__ gamma, const float* __restrict__ beta)
{
    float* p = g_o + (long)blockIdx.x*INNER;
    const int tid = threadIdx.x;

    float4 v = ((const float4*)p)[tid];
    float s  = v.x + v.y + v.z + v.w;
    float sq = v.x*v.x + v.y*v.y + v.z*v.z + v.w*v.w;

    #pragma unroll
    for (int o = 16; o > 0; o >>= 1) {
        s  += __shfl_down_sync(0xffffffffu, s,  o);
        sq += __shfl_down_sync(0xffffffffu, sq, o);
    }
    __shared__ float sh[16];
    __shared__ float mu_s, inv_s;
    int wid = tid >> 5, lane = tid & 31;
    if (lane == 0) { sh[wid] = s; sh[8 + wid] = sq; }
    __syncthreads();
    if (tid == 0) {
        float t = 0.f, tq = 0.f;
        #pragma unroll
        for (int i = 0; i < 8; i++) { t += sh[i]; tq += sh[8+i]; }
        float mu = t * (1.f/INNER);
        float var = tq * (1.f/INNER) - mu*mu;
        mu_s = mu;
        inv_s = rsqrtf(fmaxf(var, 0.f) + LN_EPS);
    }
    __syncthreads();

    float mu = mu_s, inv = inv_s;
    float4 g = ((const float4*)gamma)[tid];
    float4 bt = ((const float4*)beta)[tid];
    v.x = (v.x - mu)*inv*g.x + bt.x;
    v.y = (v.y - mu)*inv*g.y + bt.y;
    v.z = (v.z - mu)*inv*g.z + bt.z;
    v.w = (v.w - mu)*inv*g.w + bt.w;
    ((float4*)p)[tid] = v;
}

// =====================================================================
// Kernel 6: out = LN(o) @ w_out + b_out  (same SGEMM, N=1024)
// =====================================================================
__global__ __launch_bounds__(256)
void out_gemm(const float* __restrict__ Bm, const float* __restrict__ bias,
              float* __restrict__ C)
{
    __shared__ float As[8][128];
    __shared__ float Bs[8][128];

    const int bm = blockIdx.y;
    const int bn = blockIdx.x;          // 0..7
    const int tid = threadIdx.x;

    const int arow = tid >> 1;
    const int acol = (tid & 1) << 2;
    const int brow = tid >> 5;
    const int bcol = (tid & 31) << 2;
    const int ty = tid >> 4;
    const int tx = tid & 15;

    float acc[8][8];
    #pragma unroll
    for (int i = 0; i < 8; i++)
        #pragma unroll
        for (int j = 0; j < 8; j++) acc[i][j] = 0.f;

    const float* Aptr = g_o + (long)(bm*128 + arow)*INNER + acol;
    const float* Bptr = Bm + (long)brow*DIM + bn*128 + bcol;

    for (int k0 = 0; k0 < INNER; k0 += 8) {
        float4 av = *(const float4*)(Aptr + k0);
        As[acol+0][arow] = av.x;
        As[acol+1][arow] = av.y;
        As[acol+2][arow] = av.z;
        As[acol+3][arow] = av.w;
        *(float4*)&Bs[brow][bcol] = *(const float4*)(Bptr + (long)k0*DIM);
        __syncthreads();

        #pragma unroll
        for (int kk = 0; kk < 8; kk++) {
            float4 a0 = *(const float4*)&As[kk][ty*4];
            float4 a1 = *(const float4*)&As[kk][ty*4 + 64];
            float4 b0 = *(const float4*)&Bs[kk][tx*4];
            float4 b1 = *(const float4*)&Bs[kk][tx*4 + 64];
            float a[8] = {a0.x,a0.y,a0.z,a0.w,a1.x,a1.y,a1.z,a1.w};
            float b[8] = {b0.x,b0.y,b0.z,b0.w,b1.x,b1.y,b1.z,b1.w};
            #pragma unroll
            for (int i = 0; i < 8; i++)
                #pragma unroll
                for (int j = 0; j < 8; j++)
                    acc[i][j] = fmaf(a[i], b[j], acc[i][j]);
        }
        __syncthreads();
    }

    #pragma unroll
    for (int i = 0; i < 8; i++) {
        int gm = bm*128 + (i < 4 ? ty*4 + i : 64 + ty*4 + (i-4));
        #pragma unroll
        for (int j = 0; j < 8; j++) {
            int gn = bn*128 + (j < 4 ? tx*4 + j : 64 + tx*4 + (j-4));
            C[(long)gm*DIM + gn] = acc[i][j] + bias[gn];
        }
    }
}

// =====================================================================
// launcher
// =====================================================================
extern "C" void kernel_launch(void* const* d_in, const int* in_sizes, int n_in,
                              void* d_out, int out_size)
{
    const float* x     = (const float*)d_in[0];
    const float* w_qkv = (const float*)d_in[1];
    const float* gamma = (const float*)d_in[2];
    const float* beta  = (const float*)d_in[3];
    const float* w_out = (const float*)d_in[4];
    const float* b_out = (const float*)d_in[5];
    float* out = (float*)d_out;

    // 1: qkv GEMM + relu + head scatter
    qkv_gemm<<<dim3(QKVN/128, MROWS/128), 256>>>(x, w_qkv);
    // 2: kv partials (64 bh * 8 splits)
    kv_partial<<<512, 256>>>();
    // 3: reduce splits
    kv_reduce<<<1024, 256>>>();
    // 4: o = q @ kv
    o_gemm<<<2048, 256>>>();
    // 5: LayerNorm in place
    layernorm_rows<<<MROWS, 256>>>(gamma, beta);
    // 6: out projection + bias
    out_gemm<<<dim3(DIM/128, MROWS/128), 256>>>(w_out, b_out, out);
}

// round 3
// speedup vs baseline: 2.5706x; 2.5706x over previous
#include <cuda_runtime.h>
#include <cuda_bf16.h>
#include <cstdint>

// ---------------- problem constants ----------------
#define BATCH 4
#define SEQ   4096
#define DIM   1024
#define HEADS 16
#define DHEAD 64
#define INNER 1024
#define MROWS (BATCH*SEQ)   // 16384
#define QKVN  (3*INNER)     // 3072
#define LN_EPS 1e-5f

// ---------------- scratch (device globals; no allocs allowed) ----------------
__device__ float g_q[BATCH*HEADS*SEQ*DHEAD];
__device__ float g_k[BATCH*HEADS*SEQ*DHEAD];
__device__ float g_v[BATCH*HEADS*SEQ*DHEAD];
__device__ float g_kvp[64*8*64*64];
__device__ float g_kv[64*64*64];
__device__ float g_o[MROWS*INNER];

// bf16 split operands
__device__ __nv_bfloat16 g_xhi[MROWS*DIM];      // A (x, later LN(o))
__device__ __nv_bfloat16 g_xlo[MROWS*DIM];
__device__ __nv_bfloat16 g_w1hi[QKVN*DIM];      // w_qkv^T  [N][K]
__device__ __nv_bfloat16 g_w1lo[QKVN*DIM];
__device__ __nv_bfloat16 g_w2hi[DIM*DIM];       // w_out^T  [N][K]
__device__ __nv_bfloat16 g_w2lo[DIM*DIM];

// =====================================================================
// helpers
// =====================================================================
__device__ __forceinline__ uint32_t smem_u32(const void* p) {
    uint32_t a;
    asm("{ .reg .u64 t; cvta.to.shared.u64 t, %1; cvt.u32.u64 %0, t; }"
        : "=r"(a) : "l"(p));
    return a;
}

__device__ __forceinline__ void cpa16(uint32_t s, const void* g) {
    asm volatile("cp.async.cg.shared.global [%0], [%1], 16;"
                 :: "r"(s), "l"(__cvta_generic_to_global(g)) : "memory");
}

__device__ __forceinline__ void ldm_x4(uint32_t addr, uint32_t* r) {
    asm volatile("ldmatrix.sync.aligned.m8n8.x4.shared.b16 {%0,%1,%2,%3}, [%4];"
        : "=r"(r[0]), "=r"(r[1]), "=r"(r[2]), "=r"(r[3]) : "r"(addr));
}

__device__ __forceinline__ void mma16816(float* d, const uint32_t* a, const uint32_t* b) {
    asm volatile("mma.sync.aligned.m16n8k16.row.col.f32.bf16.bf16.f32 "
        "{%0,%1,%2,%3}, {%4,%5,%6,%7}, {%8,%9}, {%0,%1,%2,%3};"
        : "+f"(d[0]), "+f"(d[1]), "+f"(d[2]), "+f"(d[3])
        : "r"(a[0]), "r"(a[1]), "r"(a[2]), "r"(a[3]), "r"(b[0]), "r"(b[1]));
}

__device__ __forceinline__ void split1(float f, __nv_bfloat16& h, __nv_bfloat16& l) {
    h = __float2bfloat16(f);
    l = __float2bfloat16(f - __bfloat162float(h));
}

// =====================================================================
// conversion kernels
// =====================================================================
__global__ __launch_bounds__(256)
void cvt_split(const float* __restrict__ in)
{
    long i = (long)blockIdx.x*256 + threadIdx.x;   // float4 index
    float4 v = ((const float4*)in)[i];
    __nv_bfloat16 h0,h1,h2,h3,l0,l1,l2,l3;
    split1(v.x,h0,l0); split1(v.y,h1,l1); split1(v.z,h2,l2); split1(v.w,h3,l3);
    __nv_bfloat162 ph0 = __halves2bfloat162(h0,h1), ph1 = __halves2bfloat162(h2,h3);
    __nv_bfloat162 pl0 = __halves2bfloat162(l0,l1), pl1 = __halves2bfloat162(l2,l3);
    ((__nv_bfloat162*)g_xhi)[i*2]   = ph0;
    ((__nv_bfloat162*)g_xhi)[i*2+1] = ph1;
    ((__nv_bfloat162*)g_xlo)[i*2]   = pl0;
    ((__nv_bfloat162*)g_xlo)[i*2+1] = pl1;
}

// transpose + split: in [K][N] fp32 -> out hi/lo [N][K] bf16
__global__ __launch_bounds__(256)
void cvt_split_trans(const float* __restrict__ in, int N, int sel)
{
    __shared__ float t[32][33];
    const int n0 = blockIdx.x*32, k0 = blockIdx.y*32;
    const int tid = threadIdx.x;
    const int K = DIM;
    __nv_bfloat16* hi = sel ? g_w2hi : g_w1hi;
    __nv_bfloat16* lo = sel ? g_w2lo : g_w1lo;

    #pragma unroll
    for (int i = 0; i < 4; i++) {
        int r = (tid >> 5) + i*8, c = tid & 31;
        t[r][c] = in[(long)(k0+r)*N + n0 + c];
    }
    __syncthreads();
    #pragma unroll
    for (int i = 0; i < 4; i++) {
        int a = (tid >> 5) + i*8;   // local n
        int b = tid & 31;           // local k
        float f = t[b][a];
        __nv_bfloat16 h, l;
        split1(f, h, l);
        hi[(long)(n0+a)*K + k0 + b] = h;
        lo[(long)(n0+a)*K + k0 + b] = l;
    }
}

// =====================================================================
// bf16x3 mma.sync GEMM:  C[M][Nall] = A[M][1024] @ B^T  (B stored [N][K])
//   tile 128x128x64, 8 warps (64x32 each), double-buffered cp.async
//   mode 0: relu + scatter to g_q/g_k/g_v   (B = w1, Nall=3072)
//   mode 1: +bias, write Cout row-major      (B = w2, Nall=1024)
// =====================================================================
#define SM_AHI 0
#define SM_ALO 16384
#define SM_BHI 32768
#define SM_BLO 49152
#define STAGEB 65536
#define GEMM_SMEM (2*STAGEB)

__global__ __launch_bounds__(256, 1)
void mma_gemm(const float* __restrict__ bias, float* __restrict__ Cout, int mode)
{
    extern __shared__ char smem[];
    const uint32_t sb = smem_u32(smem);
    const int tid  = threadIdx.x;
    const int lane = tid & 31, wid = tid >> 5;
    const int wm = wid >> 2, wn = wid & 3;          // 2 x 4 warp grid
    const int m0 = blockIdx.y * 128;
    const int n0 = blockIdx.x * 128;

    const __nv_bfloat16* Ahi = g_xhi;
    const __nv_bfloat16* Alo = g_xlo;
    const __nv_bfloat16* Bhi = mode ? g_w2hi : g_w1hi;
    const __nv_bfloat16* Blo = mode ? g_w2lo : g_w1lo;

    // per-thread load geometry: 4 chunks of 16B per tile per stage
    const int lrow = tid >> 3;            // base row for chunk 0 is tid>>3? recompute per chunk
    (void)lrow;

    auto issue = [&](int buf, int k0) {
        const uint32_t so = sb + buf*STAGEB;
        #pragma unroll
        for (int i = 0; i < 4; i++) {
            int cid = tid + i*256;        // 0..1023
            int row = cid >> 3, c16 = cid & 7;
            uint32_t off = row*128 + c16*16;
            uint32_t sw = off ^ ((off >> 3) & 0x70);
            long ka = (long)(m0 + row)*DIM + k0 + c16*8;
            long kb = (long)(n0 + row)*DIM + k0 + c16*8;
            cpa16(so + SM_AHI + sw, Ahi + ka);
            cpa16(so + SM_ALO + sw, Alo + ka);
            cpa16(so + SM_BHI + sw, Bhi + kb);
            cpa16(so + SM_BLO + sw, Blo + kb);
        }
        asm volatile("cp.async.commit_group;" ::: "memory");
    };

    float acc[4][4][4];
    #pragma unroll
    for (int a = 0; a < 4; a++)
        #pragma unroll
        for (int b = 0; b < 4; b++)
            #pragma unroll
            for (int d = 0; d < 4; d++) acc[a][b][d] = 0.f;

    issue(0, 0);

    #pragma unroll 1
    for (int c = 0; c < 16; c++) {
        if (c + 1 < 16) {
            issue((c+1) & 1, (c+1)*64);
            asm volatile("cp.async.wait_group 1;" ::: "memory");
        } else {
            asm volatile("cp.async.wait_group 0;" ::: "memory");
        }
        __syncthreads();

        const uint32_t so = sb + (c & 1)*STAGEB;

        #pragma unroll
        for (int k16 = 0; k16 < 4; k16++) {
            uint32_t ah[4][4], al[4][4], bh[2][4], bl[2][4];
            {
                const int r  = lane & 15;
                const int kb = (k16*16 + ((lane >> 4) & 1)*8) * 2;
                #pragma unroll
                for (int mf = 0; mf < 4; mf++) {
                    uint32_t off = (uint32_t)(wm*64 + mf*16 + r)*128 + kb;
                    uint32_t sw = off ^ ((off >> 3) & 0x70);
                    ldm_x4(so + SM_AHI + sw, ah[mf]);
                    ldm_x4(so + SM_ALO + sw, al[mf]);
                }
            }
            {
                const int nn = (lane & 7) + ((lane >> 4) & 1)*8;
                const int kb = (k16*16 + ((lane >> 3) & 1)*8) * 2;
                #pragma unroll
                for (int np = 0; np < 2; np++) {
                    uint32_t off = (uint32_t)(wn*32 + np*16 + nn)*128 + kb;
                    uint32_t sw = off ^ ((off >> 3) & 0x70);
                    ldm_x4(so + SM_BHI + sw, bh[np]);
                    ldm_x4(so + SM_BLO + sw, bl[np]);
                }
            }
            #pragma unroll
            for (int mf = 0; mf < 4; mf++)
                #pragma unroll
                for (int nf = 0; nf < 4; nf++) {
                    const uint32_t* bhp = &bh[nf >> 1][(nf & 1)*2];
                    const uint32_t* blp = &bl[nf >> 1][(nf & 1)*2];
                    mma16816(acc[mf][nf], ah[mf], bhp);
                    mma16816(acc[mf][nf], ah[mf], blp);
                    mma16816(acc[mf][nf], al[mf], bhp);
                }
        }
        __syncthreads();
    }

    // ---- epilogue: stage accumulators to smem, coalesced store ----
    float* stg = (float*)smem;              // [128][132]
    #pragma unroll
    for (int mf = 0; mf < 4; mf++)
        #pragma unroll
        for (int nf = 0; nf < 4; nf++) {
            int row = wm*64 + mf*16 + (lane >> 2);
            int col = wn*32 + nf*8 + (lane & 3)*2;
            stg[row*132 + col]       = acc[mf][nf][0];
            stg[row*132 + col + 1]   = acc[mf][nf][1];
            stg[(row+8)*132 + col]   = acc[mf][nf][2];
            stg[(row+8)*132 + col+1] = acc[mf][nf][3];
        }
    __syncthreads();

    #pragma unroll
    for (int i = 0; i < 16; i++) {
        int slot = tid + i*256;
        int row = slot >> 5, c4 = slot & 31;
        float4 v;
        v.x = stg[row*132 + c4*4 + 0];
        v.y = stg[row*132 + c4*4 + 1];
        v.z = stg[row*132 + c4*4 + 2];
        v.w = stg[row*132 + c4*4 + 3];
        int gm = m0 + row;
        int gn = n0 + c4*4;
        if (mode == 0) {
            int part = gn >> 10;
            int inner = gn & 1023;
            int h = inner >> 6, d = inner & 63;
            int b = gm >> 12, s = gm & 4095;
            long dst = (((long)(b*16 + h))*4096 + s)*64 + d;
            if (part == 0) {
                v.x = fmaxf(v.x, 0.f); v.y = fmaxf(v.y, 0.f);
                v.z = fmaxf(v.z, 0.f); v.w = fmaxf(v.w, 0.f);
                *(float4*)(g_q + dst) = v;
            } else if (part == 1) {
                v.x = fmaxf(v.x, 0.f); v.y = fmaxf(v.y, 0.f);
                v.z = fmaxf(v.z, 0.f); v.w = fmaxf(v.w, 0.f);
                *(float4*)(g_k + dst) = v;
            } else {
                *(float4*)(g_v + dst) = v;
            }
        } else {
            float4 bs = *(const float4*)(bias + gn);
            v.x += bs.x; v.y += bs.y; v.z += bs.z; v.w += bs.w;
            *(float4*)(Cout + (long)gm*DIM + gn) = v;
        }
    }
}

// =====================================================================
// kv partials / reduce / o_gemm (fp32, unchanged)
// =====================================================================
__global__ __launch_bounds__(256)
void kv_partial()
{
    const int bh = blockIdx.x >> 3;
    const int split = blockIdx.x & 7;
    __shared__ float Ks[32][64];
    __shared__ float Vs[32][64];

    const int tid = threadIdx.x;
    const int tm = (tid >> 4) << 2;
    const int tn = (tid & 15) << 2;
    float acc[4][4] = {{0.f}};

    const float* kbase = g_k + ((long)bh*SEQ + split*512)*DHEAD;
    const float* vbase = g_v + ((long)bh*SEQ + split*512)*DHEAD;

    for (int n0 = 0; n0 < 512; n0 += 32) {
        #pragma unroll
        for (int r = 0; r < 2; r++) {
            int idx = tid + r*256;
            int row = idx >> 4;
            int col = (idx & 15) << 2;
            *(float4*)&Ks[row][col] = *(const float4*)(kbase + (long)(n0+row)*DHEAD + col);
            *(float4*)&Vs[row][col] = *(const float4*)(vbase + (long)(n0+row)*DHEAD + col);
        }
        __syncthreads();
        #pragma unroll
        for (int nn = 0; nn < 32; nn++) {
            float4 a = *(const float4*)&Ks[nn][tm];
            float4 b = *(const float4*)&Vs[nn][tn];
            float av[4] = {a.x,a.y,a.z,a.w};
            float bv[4] = {b.x,b.y,b.z,b.w};
            #pragma unroll
            for (int i = 0; i < 4; i++)
                #pragma unroll
                for (int j = 0; j < 4; j++)
                    acc[i][j] = fmaf(av[i], bv[j], acc[i][j]);
        }
        __syncthreads();
    }

    float* dst = g_kvp + (long)blockIdx.x*4096;
    #pragma unroll
    for (int i = 0; i < 4; i++)
        #pragma unroll
        for (int j = 0; j < 4; j++)
            dst[(tm+i)*64 + tn + j] = acc[i][j];
}

__global__ void kv_reduce()
{
    int idx = blockIdx.x*256 + threadIdx.x;
    int bh = idx >> 12;
    int rem = idx & 4095;
    float s = 0.f;
    #pragma unroll
    for (int sp = 0; sp < 8; sp++)
        s += g_kvp[((long)(bh*8 + sp))*4096 + rem];
    g_kv[idx] = s;
}

__global__ __launch_bounds__(256)
void o_gemm()
{
    const int bh = blockIdx.x >> 5;
    const int mt = blockIdx.x & 31;
    const int b = bh >> 4, h = bh & 15;

    __shared__ float KVs[64][64];
    __shared__ float Qs[128][64];

    const int tid = threadIdx.x;

    #pragma unroll
    for (int r = 0; r < 4; r++) {
        int idx = tid + r*256;
        int row = idx >> 4;
        int col = (idx & 15) << 2;
        *(float4*)&KVs[row][col] = *(const float4*)(g_kv + (long)bh*4096 + row*64 + col);
    }
    const float* qbase = g_q + ((long)bh*SEQ + mt*128)*DHEAD;
    #pragma unroll
    for (int r = 0; r < 8; r++) {
        int idx = tid + r*256;
        int row = idx >> 4;
        int col = (idx & 15) << 2;
        *(float4*)&Qs[row][col] = *(const float4*)(qbase + (long)row*DHEAD + col);
    }
    __syncthreads();

    const int ty = tid >> 4;
    const int tx = tid & 15;
    float acc[8][4] = {{0.f}};

    #pragma unroll 8
    for (int kk = 0; kk < 64; kk++) {
        float4 bv = *(const float4*)&KVs[kk][tx*4];
        float bb[4] = {bv.x,bv.y,bv.z,bv.w};
        #pragma unroll
        for (int i = 0; i < 8; i++) {
            float a = Qs[ty*8 + i][kk];
            #pragma unroll
            for (int j = 0; j < 4; j++)
                acc[i][j] = fmaf(a, bb[j], acc[i][j]);
        }
    }

    #pragma unroll
    for (int i = 0; i < 8; i++) {
        long row = (long)(b*SEQ + mt*128 + ty*8 + i);
        float* dst = g_o + row*INNER + h*DHEAD + tx*4;
        float4 v = {acc[i][0], acc[i][1], acc[i][2], acc[i][3]};
        *(float4*)dst = v;
    }
}

// =====================================================================
// LayerNorm: reads g_o fp32, writes bf16 hi/lo into g_xhi/g_xlo (A of GEMM2)
// =====================================================================
__global__ __launch_bounds__(256)
void layernorm_rows(const float* __restrict__ gamma, const float* __restrict__ beta)
{
    const float* p = g_o + (long)blockIdx.x*INNER;
    const int tid = threadIdx.x;

    float4 v = ((const float4*)p)[tid];
    float s  = v.x + v.y + v.z + v.w;
    float sq = v.x*v.x + v.y*v.y + v.z*v.z + v.w*v.w;

    #pragma unroll
    for (int o = 16; o > 0; o >>= 1) {
        s  += __shfl_down_sync(0xffffffffu, s,  o);
        sq += __shfl_down_sync(0xffffffffu, sq, o);
    }
    __shared__ float sh[16];
    __shared__ float mu_s, inv_s;
    int wid = tid >> 5, lane = tid & 31;
    if (lane == 0) { sh[wid] = s; sh[8 + wid] = sq; }
    __syncthreads();
    if (tid == 0) {
        float t = 0.f, tq = 0.f;
        #pragma unroll
        for (int i = 0; i < 8; i++) { t += sh[i]; tq += sh[8+i]; }
        float mu = t * (1.f/INNER);
        float var = tq * (1.f/INNER) - mu*mu;
        mu_s = mu;
        inv_s = rsqrtf(fmaxf(var, 0.f) + LN_EPS);
    }
    __syncthreads();

    float mu = mu_s, inv = inv_s;
    float4 g = ((const float4*)gamma)[tid];
    float4 bt = ((const float4*)beta)[tid];
    float f0 = (v.x - mu)*inv*g.x + bt.x;
    float f1 = (v.y - mu)*inv*g.y + bt.y;
    float f2 = (v.z - mu)*inv*g.z + bt.z;
    float f3 = (v.w - mu)*inv*g.w + bt.w;

    __nv_bfloat16 h0,h1,h2,h3,l0,l1,l2,l3;
    split1(f0,h0,l0); split1(f1,h1,l1); split1(f2,h2,l2); split1(f3,h3,l3);
    long base = (long)blockIdx.x*INNER + tid*4;
    ((__nv_bfloat162*)(g_xhi + base))[0] = __halves2bfloat162(h0,h1);
    ((__nv_bfloat162*)(g_xhi + base))[1] = __halves2bfloat162(h2,h3);
    ((__nv_bfloat162*)(g_xlo + base))[0] = __halves2bfloat162(l0,l1);
    ((__nv_bfloat162*)(g_xlo + base))[1] = __halves2bfloat162(l2,l3);
}

// =====================================================================
// launcher
// =====================================================================
extern "C" void kernel_launch(void* const* d_in, const int* in_sizes, int n_in,
                              void* d_out, int out_size)
{
    const float* x     = (const float*)d_in[0];
    const float* w_qkv = (const float*)d_in[1];
    const float* gamma = (const float*)d_in[2];
    const float* beta  = (const float*)d_in[3];
    const float* w_out = (const float*)d_in[4];
    const float* b_out = (const float*)d_in[5];
    float* out = (float*)d_out;

    cudaFuncSetAttribute(mma_gemm, cudaFuncAttributeMaxDynamicSharedMemorySize, GEMM_SMEM);

    // conversions
    cvt_split<<<MROWS*DIM/1024, 256>>>(x);                       // x -> g_xhi/g_xlo
    cvt_split_trans<<<dim3(QKVN/32, DIM/32), 256>>>(w_qkv, QKVN, 0);
    cvt_split_trans<<<dim3(DIM/32,  DIM/32), 256>>>(w_out,  DIM, 1);

    // 1: qkv = x @ w_qkv  (bf16x3 mma.sync) + relu + head scatter
    mma_gemm<<<dim3(QKVN/128, MROWS/128), 256, GEMM_SMEM>>>(nullptr, nullptr, 0);
    // 2-3: kv = relu(k)^T v
    kv_partial<<<512, 256>>>();
    kv_reduce<<<1024, 256>>>();
    // 4: o = q @ kv
    o_gemm<<<2048, 256>>>();
    // 5: LayerNorm -> bf16 hi/lo (A of GEMM2)
    layernorm_rows<<<MROWS, 256>>>(gamma, beta);
    // 6: out = LN(o) @ w_out + b_out  (bf16x3 mma.sync)
    mma_gemm<<<dim3(DIM/128, MROWS/128), 256, GEMM_SMEM>>>(b_out, out, 1);
}